// round 10
// baseline (speedup 1.0000x reference)
#include <cuda_runtime.h>
#include <cuda_fp16.h>
#include <math.h>
#include <stdint.h>

#define N_TOT 8192
#define B_HALF 4096
#define D 128
#define NWORK 2080
// sqrt(log2(e)/T), T=0.5: fold temperature+log2e into normalization so the
// Gram accumulator is sim in log2-units: exp(sim)=ex2(acc), sim=acc*ln2.
#define VSCALE 1.6986436f
#define LN2F 0.69314718055994531f

// ---------------- device globals ----------------
__device__ __half g_vh[N_TOT * D];
__device__ float g_rowsum[N_TOT];
__device__ float g_pos[N_TOT];
__device__ unsigned int g_ctr;

// ---------------- helpers ----------------
__device__ __forceinline__ uint32_t smem_u32(const void* p) {
    uint32_t a;
    asm("{ .reg .u64 t; cvta.to.shared.u64 t, %1; cvt.u32.u64 %0, t; }" : "=r"(a) : "l"(p));
    return a;
}
__device__ __forceinline__ uint32_t ex2h2(uint32_t x) {
    uint32_t y; asm("ex2.approx.f16x2 %0, %1;" : "=r"(y) : "r"(x)); return y;
}
__device__ __forceinline__ uint32_t hadd2(uint32_t a, uint32_t b) {
    uint32_t d; asm("add.rn.f16x2 %0, %1, %2;" : "=r"(d) : "r"(a), "r"(b)); return d;
}
__device__ __forceinline__ float2 h22f2(uint32_t u) {
    __half2 h = *reinterpret_cast<__half2*>(&u);
    return __half22float2(h);
}
__device__ __forceinline__ void ldsm_x4(uint32_t* r, uint32_t a) {
    asm volatile("ldmatrix.sync.aligned.m8n8.x4.shared.b16 {%0,%1,%2,%3}, [%4];"
                 : "=r"(r[0]), "=r"(r[1]), "=r"(r[2]), "=r"(r[3]) : "r"(a));
}
__device__ __forceinline__ void ldsm_x4t(uint32_t* r, uint32_t a) {
    asm volatile("ldmatrix.sync.aligned.m8n8.x4.trans.shared.b16 {%0,%1,%2,%3}, [%4];"
                 : "=r"(r[0]), "=r"(r[1]), "=r"(r[2]), "=r"(r[3]) : "r"(a));
}
// fp16-accumulate HMMA
__device__ __forceinline__ void mma16816h(uint32_t* d, const uint32_t* a, const uint32_t* b) {
    asm volatile(
        "mma.sync.aligned.m16n8k16.row.col.f16.f16.f16.f16 "
        "{%0,%1}, {%2,%3,%4,%5}, {%6,%7}, {%0,%1};"
        : "+r"(d[0]), "+r"(d[1])
        : "r"(a[0]), "r"(a[1]), "r"(a[2]), "r"(a[3]), "r"(b[0]), "r"(b[1]));
}
__device__ __forceinline__ void cp_async16(uint32_t saddr, const void* gptr) {
    asm volatile("cp.async.cg.shared.global [%0], [%1], 16;"
                 :: "r"(saddr), "l"(gptr) : "memory");
}

// phase buffer: 128 rows x 64 f16 (128B/row), 8 chunks of 16B, XOR-swizzled
__device__ __forceinline__ uint32_t sw_addr(uint32_t base, int row, int chunk) {
    return base + row * 128 + (((chunk ^ row) & 7) << 4);
}

// ---------------- kernels ----------------
__global__ void normalize_k(const float* __restrict__ zi,
                            const float* __restrict__ zj) {
    int gt = blockIdx.x * blockDim.x + threadIdx.x;
    int warp = gt >> 5, lane = gt & 31;
    if (gt < N_TOT) g_rowsum[gt] = 0.0f;
    if (gt == 0) g_ctr = 0u;
    if (warp >= N_TOT) return;
    const float* src = (warp < B_HALF) ? (zi + (size_t)warp * D)
                                       : (zj + (size_t)(warp - B_HALF) * D);
    float4 a = reinterpret_cast<const float4*>(src)[lane];
    float ss = a.x * a.x + a.y * a.y + a.z * a.z + a.w * a.w;
#pragma unroll
    for (int o = 16; o; o >>= 1) ss += __shfl_xor_sync(0xffffffffu, ss, o);
    float s = VSCALE / fmaxf(sqrtf(ss), 1e-8f);
    __half2 h0 = __floats2half2_rn(a.x * s, a.y * s);
    __half2 h1 = __floats2half2_rn(a.z * s, a.w * s);
    uint2 pk = make_uint2(*reinterpret_cast<uint32_t*>(&h0),
                          *reinterpret_cast<uint32_t*>(&h1));
    reinterpret_cast<uint2*>(g_vh + (size_t)warp * D)[lane] = pk;
}

// smem: A ph0 | A ph1 | B ph0 | B ph1, 16KB each
#define SMEM_BYTES 65536

// 512 threads = 16 warps in a 4x4 grid; each warp computes 32x32.
__global__ void __launch_bounds__(512, 2) simclr_mma_k(float* __restrict__ out) {
    // wrapped-diagonal triangle map: each unordered block pair exactly once
    int x = blockIdx.x, y = blockIdx.y;
    if (y == 32 && x >= 32) return;
    int c = (x + y) & 63;
    const int rb = min(x, c), cb = max(x, c);

    extern __shared__ char dynsm[];
    __shared__ float smrow[128];
    __shared__ float smcol[128];
    __shared__ unsigned int s_last;
    const uint32_t SA = smem_u32(dynsm);
    const bool self_tile = (rb == cb);
    const bool pos_tile = (cb == rb + 32);
    const uint32_t SB = self_tile ? SA : SA + 32768;

    const int tid = threadIdx.x, wid = tid >> 5, lane = tid & 31;
    const int wr = wid >> 2, wc = wid & 3;

    if (tid < 128) { smrow[tid] = 0.0f; smcol[tid] = 0.0f; }

    // ---- issue ALL tile loads via cp.async: group 0 = phase 0, group 1 = phase 1
    {
        const uint4* ga = reinterpret_cast<const uint4*>(g_vh) + (size_t)rb * 128 * 16;
        const uint4* gb = reinterpret_cast<const uint4*>(g_vh) + (size_t)cb * 128 * 16;
#pragma unroll
        for (int p = 0; p < 2; p++) {
#pragma unroll
            for (int i = 0; i < 2; i++) {
                int idx = tid + i * 512;           // 0..1023
                int row = idx >> 3, ch = idx & 7;  // row 0..127, chunk 0..7
                cp_async16(sw_addr(SA + p * 16384, row, ch), ga + row * 16 + p * 8 + ch);
                if (!self_tile)
                    cp_async16(sw_addr(SB + p * 16384, row, ch), gb + row * 16 + p * 8 + ch);
            }
            asm volatile("cp.async.commit_group;" ::: "memory");
        }
    }

    uint32_t acc[2][4][2];
#pragma unroll
    for (int mt = 0; mt < 2; mt++)
#pragma unroll
        for (int nt = 0; nt < 4; nt++) { acc[mt][nt][0] = 0u; acc[mt][nt][1] = 0u; }

    const int g = lane >> 3;
    const int arow_off = (lane & 7) + ((g & 1) << 3);
    const int achunk_off = g >> 1;
    const int brow_off = (lane & 7) + ((lane >> 4) & 1) * 8;
    const int bchunk_off = (lane >> 3) & 1;

#pragma unroll
    for (int p = 0; p < 2; p++) {
        if (p == 0) {
            asm volatile("cp.async.wait_group 1;" ::: "memory");
        } else {
            asm volatile("cp.async.wait_group 0;" ::: "memory");
        }
        __syncthreads();
        const uint32_t AP = SA + p * 16384;
        const uint32_t BP = SB + p * 16384;
#pragma unroll
        for (int kp = 0; kp < 4; kp++) {
            uint32_t afr[2][4];
#pragma unroll
            for (int mt = 0; mt < 2; mt++) {
                int row = wr * 32 + mt * 16 + arow_off;
                ldsm_x4(afr[mt], sw_addr(AP, row, 2 * kp + achunk_off));
            }
            uint32_t bfr[4][2];
#pragma unroll
            for (int nb = 0; nb < 2; nb++) {
                uint32_t r4[4];
                int row = wc * 32 + nb * 16 + brow_off;
                ldsm_x4t(r4, sw_addr(BP, row, 2 * kp + bchunk_off));
                bfr[2 * nb][0] = r4[0]; bfr[2 * nb][1] = r4[1];
                bfr[2 * nb + 1][0] = r4[2]; bfr[2 * nb + 1][1] = r4[3];
            }
#pragma unroll
            for (int mt = 0; mt < 2; mt++)
#pragma unroll
                for (int nt = 0; nt < 4; nt++)
                    mma16816h(acc[mt][nt], afr[mt], bfr[nt]);
        }
    }

    // -------- epilogue --------
    const int lr4 = lane >> 2;
    const int lc2 = (lane & 3) * 2;

    if (self_tile | pos_tile) {
        // exact f32 path for the 96 special CTAs
        float csA[4] = {0.f, 0.f, 0.f, 0.f};
        float csB[4] = {0.f, 0.f, 0.f, 0.f};
#pragma unroll
        for (int mt = 0; mt < 2; mt++) {
            float rs0 = 0.0f, rs1 = 0.0f;
            int lrow0 = wr * 32 + mt * 16 + lr4;
#pragma unroll
            for (int nt = 0; nt < 4; nt++) {
                float2 v01 = h22f2(acc[mt][nt][0]);
                float2 v23 = h22f2(acc[mt][nt][1]);
                float e0 = exp2f(v01.x), e1 = exp2f(v01.y);
                float e2 = exp2f(v23.x), e3 = exp2f(v23.y);
                int lcol0 = wc * 32 + nt * 8 + lc2;
                if (self_tile) {
                    if (lcol0 == lrow0) e0 = 0.0f;
                    if (lcol0 + 1 == lrow0) e1 = 0.0f;
                    if (lcol0 == lrow0 + 8) e2 = 0.0f;
                    if (lcol0 + 1 == lrow0 + 8) e3 = 0.0f;
                } else {
                    int grR = rb * 128 + lrow0;
                    int grC = cb * 128 + lrow0;
                    if (lcol0 == lrow0)     { float p2 = v01.x * LN2F; g_pos[grR] = p2; g_pos[grC] = p2; }
                    if (lcol0 + 1 == lrow0) { float p2 = v01.y * LN2F; g_pos[grR] = p2; g_pos[grC] = p2; }
                    if (lcol0 == lrow0 + 8)     { float p2 = v23.x * LN2F; g_pos[grR + 8] = p2; g_pos[grC + 8] = p2; }
                    if (lcol0 + 1 == lrow0 + 8) { float p2 = v23.y * LN2F; g_pos[grR + 8] = p2; g_pos[grC + 8] = p2; }
                }
                rs0 += e0 + e1;
                rs1 += e2 + e3;
                csA[nt] += e0 + e2;
                csB[nt] += e1 + e3;
            }
            rs0 += __shfl_xor_sync(0xffffffffu, rs0, 1);
            rs0 += __shfl_xor_sync(0xffffffffu, rs0, 2);
            rs1 += __shfl_xor_sync(0xffffffffu, rs1, 1);
            rs1 += __shfl_xor_sync(0xffffffffu, rs1, 2);
            if ((lane & 3) == 0) {
                atomicAdd(&smrow[lrow0], rs0);
                atomicAdd(&smrow[lrow0 + 8], rs1);
            }
        }
        if (!self_tile) {
#pragma unroll
            for (int nt = 0; nt < 4; nt++) {
                float a = csA[nt], b2 = csB[nt];
#pragma unroll
                for (int o = 4; o <= 16; o <<= 1) {
                    a += __shfl_xor_sync(0xffffffffu, a, o);
                    b2 += __shfl_xor_sync(0xffffffffu, b2, o);
                }
                if (lane < 4) {
                    int col = wc * 32 + nt * 8 + lane * 2;
                    atomicAdd(&smcol[col], a);
                    atomicAdd(&smcol[col + 1], b2);
                }
            }
        }
    } else {
        // hot path: packed f16x2 exp + sums
        uint32_t cs[4] = {0u, 0u, 0u, 0u};
#pragma unroll
        for (int mt = 0; mt < 2; mt++) {
            uint32_t rp0 = 0u, rp1 = 0u;
#pragma unroll
            for (int nt = 0; nt < 4; nt++) {
                uint32_t e0 = ex2h2(acc[mt][nt][0]);
                uint32_t e1 = ex2h2(acc[mt][nt][1]);
                rp0 = hadd2(rp0, e0);
                rp1 = hadd2(rp1, e1);
                cs[nt] = hadd2(cs[nt], hadd2(e0, e1));
            }
            float2 f0 = h22f2(rp0);
            float2 f1 = h22f2(rp1);
            float rs0 = f0.x + f0.y, rs1 = f1.x + f1.y;
            rs0 += __shfl_xor_sync(0xffffffffu, rs0, 1);
            rs0 += __shfl_xor_sync(0xffffffffu, rs0, 2);
            rs1 += __shfl_xor_sync(0xffffffffu, rs1, 1);
            rs1 += __shfl_xor_sync(0xffffffffu, rs1, 2);
            int lrow0 = wr * 32 + mt * 16 + lr4;
            if ((lane & 3) == 0) {
                atomicAdd(&smrow[lrow0], rs0);
                atomicAdd(&smrow[lrow0 + 8], rs1);
            }
        }
#pragma unroll
        for (int nt = 0; nt < 4; nt++) {
            float2 cf = h22f2(cs[nt]);
            float a = cf.x, b2 = cf.y;
#pragma unroll
            for (int o = 4; o <= 16; o <<= 1) {
                a += __shfl_xor_sync(0xffffffffu, a, o);
                b2 += __shfl_xor_sync(0xffffffffu, b2, o);
            }
            if (lane < 4) {
                int col = wc * 32 + nt * 8 + lane * 2;
                atomicAdd(&smcol[col], a);
                atomicAdd(&smcol[col + 1], b2);
            }
        }
    }

    __syncthreads();
    if (tid < 128) {
        atomicAdd(&g_rowsum[rb * 128 + tid], smrow[tid]);
        if (!self_tile) atomicAdd(&g_rowsum[cb * 128 + tid], smcol[tid]);
    }

    // -------- last-CTA fused reduction --------
    __threadfence();
    __syncthreads();
    if (tid == 0) s_last = (atomicAdd(&g_ctr, 1u) == NWORK - 1u);
    __syncthreads();
    if (s_last) {
        float part = 0.0f;
        for (int i = tid; i < N_TOT; i += 512)
            part += logf(g_rowsum[i]) - g_pos[i];
#pragma unroll
        for (int o = 16; o; o >>= 1) part += __shfl_xor_sync(0xffffffffu, part, o);
        if (lane == 0) smrow[wid] = part;
        __syncthreads();
        if (tid == 0) {
            float s = 0.0f;
#pragma unroll
            for (int w = 0; w < 16; w++) s += smrow[w];
            out[0] = s * (1.0f / (float)N_TOT);
        }
    }
}

// ---------------- launch ----------------
extern "C" void kernel_launch(void* const* d_in, const int* in_sizes, int n_in,
                              void* d_out, int out_size) {
    const float* zi = (const float*)d_in[0];
    const float* zj = (const float*)d_in[1];
    float* out = (float*)d_out;

    cudaFuncSetAttribute(simclr_mma_k,
                         cudaFuncAttributeMaxDynamicSharedMemorySize, SMEM_BYTES);

    normalize_k<<<(N_TOT * 32 + 255) / 256, 256>>>(zi, zj);
    dim3 grid(64, 33);
    simclr_mma_k<<<grid, 512, SMEM_BYTES>>>(out);
}

// round 11
// speedup vs baseline: 1.3612x; 1.3612x over previous
#include <cuda_runtime.h>
#include <cuda_fp16.h>
#include <math.h>
#include <stdint.h>

#define N_TOT 8192
#define B_HALF 4096
#define D 128
#define NWORK 2080
// sqrt(log2(e)/T), T=0.5: fold temperature+log2e into normalization so the
// Gram accumulator is sim in log2-units: exp(sim)=ex2(acc), sim=acc*ln2.
#define VSCALE 1.6986436f
#define LN2F 0.69314718055994531f
#define S8Q 74.0f
#define INVQ 1.8261504e-4f   // 1/(74*74): s32 dot -> log2-units

// ---------------- device globals ----------------
__device__ uint32_t g_v8[N_TOT * 32];      // int8 rows, 128 B each
__device__ float g_rowsum[N_TOT];
__device__ float g_pos[N_TOT];
__device__ unsigned int g_ctr;

// ---------------- helpers ----------------
__device__ __forceinline__ uint32_t smem_u32(const void* p) {
    uint32_t a;
    asm("{ .reg .u64 t; cvta.to.shared.u64 t, %1; cvt.u32.u64 %0, t; }" : "=r"(a) : "l"(p));
    return a;
}
__device__ __forceinline__ uint32_t pack_h2(float lo, float hi) {
    uint32_t d; asm("cvt.rn.f16x2.f32 %0, %1, %2;" : "=r"(d) : "f"(hi), "f"(lo)); return d;
}
__device__ __forceinline__ uint32_t ex2h2(uint32_t x) {
    uint32_t y; asm("ex2.approx.f16x2 %0, %1;" : "=r"(y) : "r"(x)); return y;
}
__device__ __forceinline__ uint32_t hadd2(uint32_t a, uint32_t b) {
    uint32_t d; asm("add.rn.f16x2 %0, %1, %2;" : "=r"(d) : "r"(a), "r"(b)); return d;
}
__device__ __forceinline__ float2 h22f2(uint32_t u) {
    __half2 h = *reinterpret_cast<__half2*>(&u);
    return __half22float2(h);
}
__device__ __forceinline__ void ldsm_x4(uint32_t* r, uint32_t a) {
    asm volatile("ldmatrix.sync.aligned.m8n8.x4.shared.b16 {%0,%1,%2,%3}, [%4];"
                 : "=r"(r[0]), "=r"(r[1]), "=r"(r[2]), "=r"(r[3]) : "r"(a));
}
__device__ __forceinline__ uint32_t lds32(uint32_t a) {
    uint32_t v; asm volatile("ld.shared.b32 %0, [%1];" : "=r"(v) : "r"(a)); return v;
}
// int8 MMA, exact s32 accumulate, K=32 per instruction
__device__ __forceinline__ void mma_s8(int32_t* d, const uint32_t* a,
                                       uint32_t b0, uint32_t b1) {
    asm volatile(
        "mma.sync.aligned.m16n8k32.row.col.s32.s8.s8.s32 "
        "{%0,%1,%2,%3}, {%4,%5,%6,%7}, {%8,%9}, {%0,%1,%2,%3};"
        : "+r"(d[0]), "+r"(d[1]), "+r"(d[2]), "+r"(d[3])
        : "r"(a[0]), "r"(a[1]), "r"(a[2]), "r"(a[3]), "r"(b0), "r"(b1));
}
__device__ __forceinline__ void cp_async16(uint32_t saddr, const void* gptr) {
    asm volatile("cp.async.cg.shared.global [%0], [%1], 16;"
                 :: "r"(saddr), "l"(gptr) : "memory");
}

// tile: 128 rows x 128 int8 (128B/row), 8 chunks of 16B, XOR-swizzled
__device__ __forceinline__ uint32_t sw_addr(uint32_t base, int row, int chunk) {
    return base + row * 128 + (((chunk ^ row) & 7) << 4);
}

// ---------------- kernels ----------------
__global__ void normalize_k(const float* __restrict__ zi,
                            const float* __restrict__ zj) {
    int gt = blockIdx.x * blockDim.x + threadIdx.x;
    int warp = gt >> 5, lane = gt & 31;
    if (gt < N_TOT) g_rowsum[gt] = 0.0f;
    if (gt == 0) g_ctr = 0u;
    if (warp >= N_TOT) return;
    const float* src = (warp < B_HALF) ? (zi + (size_t)warp * D)
                                       : (zj + (size_t)(warp - B_HALF) * D);
    float4 a = reinterpret_cast<const float4*>(src)[lane];
    float ss = a.x * a.x + a.y * a.y + a.z * a.z + a.w * a.w;
#pragma unroll
    for (int o = 16; o; o >>= 1) ss += __shfl_xor_sync(0xffffffffu, ss, o);
    float s = (VSCALE * S8Q) / fmaxf(sqrtf(ss), 1e-8f);
    int i0 = __float2int_rn(a.x * s), i1 = __float2int_rn(a.y * s);
    int i2 = __float2int_rn(a.z * s), i3 = __float2int_rn(a.w * s);
    uint32_t pk = (i0 & 0xff) | ((i1 & 0xff) << 8) | ((i2 & 0xff) << 16)
                | ((uint32_t)(i3 & 0xff) << 24);
    g_v8[warp * 32 + lane] = pk;
}

// smem: A tile 16KB | B tile 16KB
#define SMEM_BYTES 32768

// 256 threads = 8 warps (2x4); warp computes 64x32, processed as two 64x16
// column halves over full K (keeps s32 acc register count at 32).
__global__ void __launch_bounds__(256, 3) simclr_mma_k(float* __restrict__ out) {
    // wrapped-diagonal triangle map: each unordered block pair exactly once
    int x = blockIdx.x, y = blockIdx.y;
    if (y == 32 && x >= 32) return;
    int c = (x + y) & 63;
    const int rb = min(x, c), cb = max(x, c);

    extern __shared__ char dynsm[];
    __shared__ float smrow[128];
    __shared__ float smcol[128];
    __shared__ unsigned int s_last;
    const uint32_t SA = smem_u32(dynsm);
    const bool self_tile = (rb == cb);
    const bool pos_tile = (cb == rb + 32);
    const uint32_t SB = self_tile ? SA : SA + 16384;

    const int tid = threadIdx.x, wid = tid >> 5, lane = tid & 31;
    const int wr = wid >> 2, wc = wid & 3;

    if (tid < 128) { smrow[tid] = 0.0f; smcol[tid] = 0.0f; }

    // ---- load both tiles via one cp.async group (int8: 16KB each)
    {
        const uint4* ga = reinterpret_cast<const uint4*>(g_v8) + (size_t)rb * 1024;
        const uint4* gb = reinterpret_cast<const uint4*>(g_v8) + (size_t)cb * 1024;
#pragma unroll
        for (int i = 0; i < 4; i++) {
            int idx = tid + i * 256;           // 0..1023
            int row = idx >> 3, ch = idx & 7;
            cp_async16(sw_addr(SA, row, ch), ga + row * 8 + ch);
            if (!self_tile)
                cp_async16(sw_addr(SB, row, ch), gb + row * 8 + ch);
        }
        asm volatile("cp.async.commit_group;" ::: "memory");
    }

    const int g2 = lane >> 3;
    const int arow_off = (lane & 7) + ((g2 & 1) << 3);
    const int achunk_off = g2 >> 1;
    const int brow_off = lane >> 2;            // 0..7 within an 8-col group
    const int bbyte_off = (lane & 3) << 2;
    const int lr4 = lane >> 2;
    const int lc2 = (lane & 3) * 2;

    asm volatile("cp.async.wait_group 0;" ::: "memory");
    __syncthreads();

#pragma unroll
    for (int half = 0; half < 2; half++) {
        const int colbase = wc * 32 + half * 16;   // warp's 16-col half

        int32_t acc[4][2][4];
#pragma unroll
        for (int mt = 0; mt < 4; mt++)
#pragma unroll
            for (int nt = 0; nt < 2; nt++)
#pragma unroll
                for (int r = 0; r < 4; r++) acc[mt][nt][r] = 0;

#pragma unroll
        for (int kp = 0; kp < 4; kp++) {       // K=32 per step
            uint32_t afr[4][4];
#pragma unroll
            for (int mt = 0; mt < 4; mt++) {
                int row = wr * 64 + mt * 16 + arow_off;
                ldsm_x4(afr[mt], sw_addr(SA, row, 2 * kp + achunk_off));
            }
#pragma unroll
            for (int nt = 0; nt < 2; nt++) {
                int row = colbase + nt * 8 + brow_off;
                uint32_t b0 = lds32(sw_addr(SB, row, 2 * kp) + bbyte_off);
                uint32_t b1 = lds32(sw_addr(SB, row, 2 * kp + 1) + bbyte_off);
#pragma unroll
                for (int mt = 0; mt < 4; mt++)
                    mma_s8(acc[mt][nt], afr[mt], b0, b1);
            }
        }

        // -------- epilogue for this half --------
        if (self_tile | pos_tile) {
            float csA[2] = {0.f, 0.f}, csB[2] = {0.f, 0.f};
#pragma unroll
            for (int mt = 0; mt < 4; mt++) {
                float rs0 = 0.0f, rs1 = 0.0f;
                int lrow0 = wr * 64 + mt * 16 + lr4;
#pragma unroll
                for (int nt = 0; nt < 2; nt++) {
                    float v0 = (float)acc[mt][nt][0] * INVQ;
                    float v1 = (float)acc[mt][nt][1] * INVQ;
                    float v2 = (float)acc[mt][nt][2] * INVQ;
                    float v3 = (float)acc[mt][nt][3] * INVQ;
                    float e0 = exp2f(v0), e1 = exp2f(v1);
                    float e2 = exp2f(v2), e3 = exp2f(v3);
                    int lcol0 = colbase + nt * 8 + lc2;
                    if (self_tile) {
                        if (lcol0 == lrow0) e0 = 0.0f;
                        if (lcol0 + 1 == lrow0) e1 = 0.0f;
                        if (lcol0 == lrow0 + 8) e2 = 0.0f;
                        if (lcol0 + 1 == lrow0 + 8) e3 = 0.0f;
                    } else {
                        int grR = rb * 128 + lrow0;
                        int grC = cb * 128 + lrow0;
                        if (lcol0 == lrow0)     { float p2 = v0 * LN2F; g_pos[grR] = p2; g_pos[grC] = p2; }
                        if (lcol0 + 1 == lrow0) { float p2 = v1 * LN2F; g_pos[grR] = p2; g_pos[grC] = p2; }
                        if (lcol0 == lrow0 + 8)     { float p2 = v2 * LN2F; g_pos[grR + 8] = p2; g_pos[grC + 8] = p2; }
                        if (lcol0 + 1 == lrow0 + 8) { float p2 = v3 * LN2F; g_pos[grR + 8] = p2; g_pos[grC + 8] = p2; }
                    }
                    rs0 += e0 + e1;
                    rs1 += e2 + e3;
                    csA[nt] += e0 + e2;
                    csB[nt] += e1 + e3;
                }
                rs0 += __shfl_xor_sync(0xffffffffu, rs0, 1);
                rs0 += __shfl_xor_sync(0xffffffffu, rs0, 2);
                rs1 += __shfl_xor_sync(0xffffffffu, rs1, 1);
                rs1 += __shfl_xor_sync(0xffffffffu, rs1, 2);
                if ((lane & 3) == 0) {
                    atomicAdd(&smrow[lrow0], rs0);
                    atomicAdd(&smrow[lrow0 + 8], rs1);
                }
            }
            if (!self_tile) {
#pragma unroll
                for (int nt = 0; nt < 2; nt++) {
                    float a = csA[nt], b2 = csB[nt];
#pragma unroll
                    for (int o = 4; o <= 16; o <<= 1) {
                        a += __shfl_xor_sync(0xffffffffu, a, o);
                        b2 += __shfl_xor_sync(0xffffffffu, b2, o);
                    }
                    if (lane < 4) {
                        int col = colbase + nt * 8 + lane * 2;
                        atomicAdd(&smcol[col], a);
                        atomicAdd(&smcol[col + 1], b2);
                    }
                }
            }
        } else {
            uint32_t cs[2] = {0u, 0u};
#pragma unroll
            for (int mt = 0; mt < 4; mt++) {
                uint32_t rp0 = 0u, rp1 = 0u;
#pragma unroll
                for (int nt = 0; nt < 2; nt++) {
                    float v0 = (float)acc[mt][nt][0] * INVQ;
                    float v1 = (float)acc[mt][nt][1] * INVQ;
                    float v2 = (float)acc[mt][nt][2] * INVQ;
                    float v3 = (float)acc[mt][nt][3] * INVQ;
                    uint32_t e0 = ex2h2(pack_h2(v0, v1));
                    uint32_t e1 = ex2h2(pack_h2(v2, v3));
                    rp0 = hadd2(rp0, e0);
                    rp1 = hadd2(rp1, e1);
                    cs[nt] = hadd2(cs[nt], hadd2(e0, e1));
                }
                float2 f0 = h22f2(rp0);
                float2 f1 = h22f2(rp1);
                float rs0 = f0.x + f0.y, rs1 = f1.x + f1.y;
                rs0 += __shfl_xor_sync(0xffffffffu, rs0, 1);
                rs0 += __shfl_xor_sync(0xffffffffu, rs0, 2);
                rs1 += __shfl_xor_sync(0xffffffffu, rs1, 1);
                rs1 += __shfl_xor_sync(0xffffffffu, rs1, 2);
                int lrow0 = wr * 64 + mt * 16 + lr4;
                if ((lane & 3) == 0) {
                    atomicAdd(&smrow[lrow0], rs0);
                    atomicAdd(&smrow[lrow0 + 8], rs1);
                }
            }
#pragma unroll
            for (int nt = 0; nt < 2; nt++) {
                float2 cf = h22f2(cs[nt]);
                float a = cf.x, b2 = cf.y;
#pragma unroll
                for (int o = 4; o <= 16; o <<= 1) {
                    a += __shfl_xor_sync(0xffffffffu, a, o);
                    b2 += __shfl_xor_sync(0xffffffffu, b2, o);
                }
                if (lane < 4) {
                    int col = colbase + nt * 8 + lane * 2;
                    atomicAdd(&smcol[col], a);
                    atomicAdd(&smcol[col + 1], b2);
                }
            }
        }
    }

    __syncthreads();
    if (tid < 128) {
        atomicAdd(&g_rowsum[rb * 128 + tid], smrow[tid]);
        if (!self_tile) atomicAdd(&g_rowsum[cb * 128 + tid], smcol[tid]);
    }

    // -------- last-CTA fused reduction --------
    __threadfence();
    __syncthreads();
    if (tid == 0) s_last = (atomicAdd(&g_ctr, 1u) == NWORK - 1u);
    __syncthreads();
    if (s_last) {
        float part = 0.0f;
        for (int i = tid; i < N_TOT; i += 256)
            part += logf(g_rowsum[i]) - g_pos[i];
#pragma unroll
        for (int o = 16; o; o >>= 1) part += __shfl_xor_sync(0xffffffffu, part, o);
        if (lane == 0) smrow[wid] = part;
        __syncthreads();
        if (tid == 0) {
            float s = 0.0f;
#pragma unroll
            for (int w = 0; w < 8; w++) s += smrow[w];
            out[0] = s * (1.0f / (float)N_TOT);
        }
    }
}

// ---------------- launch ----------------
extern "C" void kernel_launch(void* const* d_in, const int* in_sizes, int n_in,
                              void* d_out, int out_size) {
    const float* zi = (const float*)d_in[0];
    const float* zj = (const float*)d_in[1];
    float* out = (float*)d_out;

    cudaFuncSetAttribute(simclr_mma_k,
                         cudaFuncAttributeMaxDynamicSharedMemorySize, SMEM_BYTES);

    normalize_k<<<(N_TOT * 32 + 255) / 256, 256>>>(zi, zj);
    dim3 grid(64, 33);
    simclr_mma_k<<<grid, 256, SMEM_BYTES>>>(out);
}

// round 12
// speedup vs baseline: 1.3621x; 1.0007x over previous
#include <cuda_runtime.h>
#include <cuda_fp16.h>
#include <math.h>
#include <stdint.h>

#define N_TOT 8192
#define B_HALF 4096
#define D 128
#define NWORK 2080
// sqrt(log2(e)/T), T=0.5: fold temperature+log2e into normalization so the
// Gram accumulator is sim in log2-units: exp(sim)=ex2(acc), sim=acc*ln2.
#define VSCALE 1.6986436f
#define LN2F 0.69314718055994531f
#define S8Q 74.0f
#define INVQ 1.8261504e-4f   // 1/(74*74): s32 dot -> log2-units

// ---------------- device globals ----------------
__device__ uint32_t g_v8[N_TOT * 32];      // int8 rows, 128 B each
__device__ float g_rowsum[N_TOT];
__device__ float g_pos[N_TOT];
__device__ unsigned int g_ctr;

// ---------------- helpers ----------------
__device__ __forceinline__ uint32_t smem_u32(const void* p) {
    uint32_t a;
    asm("{ .reg .u64 t; cvta.to.shared.u64 t, %1; cvt.u32.u64 %0, t; }" : "=r"(a) : "l"(p));
    return a;
}
__device__ __forceinline__ uint32_t pack_h2(float lo, float hi) {
    uint32_t d; asm("cvt.rn.f16x2.f32 %0, %1, %2;" : "=r"(d) : "f"(hi), "f"(lo)); return d;
}
__device__ __forceinline__ uint32_t ex2h2(uint32_t x) {
    uint32_t y; asm("ex2.approx.f16x2 %0, %1;" : "=r"(y) : "r"(x)); return y;
}
__device__ __forceinline__ uint32_t hadd2(uint32_t a, uint32_t b) {
    uint32_t d; asm("add.rn.f16x2 %0, %1, %2;" : "=r"(d) : "r"(a), "r"(b)); return d;
}
__device__ __forceinline__ float2 h22f2(uint32_t u) {
    __half2 h = *reinterpret_cast<__half2*>(&u);
    return __half22float2(h);
}
__device__ __forceinline__ void ldsm_x4(uint32_t* r, uint32_t a) {
    asm volatile("ldmatrix.sync.aligned.m8n8.x4.shared.b16 {%0,%1,%2,%3}, [%4];"
                 : "=r"(r[0]), "=r"(r[1]), "=r"(r[2]), "=r"(r[3]) : "r"(a));
}
// int8 MMA, exact s32 accumulate, K=32 per instruction
__device__ __forceinline__ void mma_s8(int32_t* d, const uint32_t* a,
                                       uint32_t b0, uint32_t b1) {
    asm volatile(
        "mma.sync.aligned.m16n8k32.row.col.s32.s8.s8.s32 "
        "{%0,%1,%2,%3}, {%4,%5,%6,%7}, {%8,%9}, {%0,%1,%2,%3};"
        : "+r"(d[0]), "+r"(d[1]), "+r"(d[2]), "+r"(d[3])
        : "r"(a[0]), "r"(a[1]), "r"(a[2]), "r"(a[3]), "r"(b0), "r"(b1));
}
__device__ __forceinline__ void cp_async16(uint32_t saddr, const void* gptr) {
    asm volatile("cp.async.cg.shared.global [%0], [%1], 16;"
                 :: "r"(saddr), "l"(gptr) : "memory");
}

// tile: 128 rows x 128 int8 (128B/row), 8 chunks of 16B, XOR-swizzled
__device__ __forceinline__ uint32_t sw_addr(uint32_t base, int row, int chunk) {
    return base + row * 128 + (((chunk ^ row) & 7) << 4);
}

// ---------------- kernels ----------------
__global__ void normalize_k(const float* __restrict__ zi,
                            const float* __restrict__ zj) {
    int gt = blockIdx.x * blockDim.x + threadIdx.x;
    int warp = gt >> 5, lane = gt & 31;
    if (gt < N_TOT) g_rowsum[gt] = 0.0f;
    if (gt == 0) g_ctr = 0u;
    if (warp >= N_TOT) return;
    const float* src = (warp < B_HALF) ? (zi + (size_t)warp * D)
                                       : (zj + (size_t)(warp - B_HALF) * D);
    float4 a = reinterpret_cast<const float4*>(src)[lane];
    float ss = a.x * a.x + a.y * a.y + a.z * a.z + a.w * a.w;
#pragma unroll
    for (int o = 16; o; o >>= 1) ss += __shfl_xor_sync(0xffffffffu, ss, o);
    float s = (VSCALE * S8Q) / fmaxf(sqrtf(ss), 1e-8f);
    int i0 = __float2int_rn(a.x * s), i1 = __float2int_rn(a.y * s);
    int i2 = __float2int_rn(a.z * s), i3 = __float2int_rn(a.w * s);
    uint32_t pk = (i0 & 0xff) | ((i1 & 0xff) << 8) | ((i2 & 0xff) << 16)
                | ((uint32_t)(i3 & 0xff) << 24);
    g_v8[warp * 32 + lane] = pk;
}

// smem: A tile 16KB | B tile 16KB
#define SMEM_BYTES 32768

// 256 threads = 8 warps (2x4); warp computes 64x32, processed as two 64x16
// column halves over full K (keeps s32 acc register count at 32).
__global__ void __launch_bounds__(256, 3) simclr_mma_k(float* __restrict__ out) {
    // wrapped-diagonal triangle map: each unordered block pair exactly once
    int x = blockIdx.x, y = blockIdx.y;
    if (y == 32 && x >= 32) return;
    int c = (x + y) & 63;
    const int rb = min(x, c), cb = max(x, c);

    extern __shared__ char dynsm[];
    __shared__ float smrow[128];
    __shared__ float smcol[128];
    __shared__ unsigned int s_last;
    const uint32_t SA = smem_u32(dynsm);
    const bool self_tile = (rb == cb);
    const bool pos_tile = (cb == rb + 32);
    const uint32_t SB = self_tile ? SA : SA + 16384;

    const int tid = threadIdx.x, wid = tid >> 5, lane = tid & 31;
    const int wr = wid >> 2, wc = wid & 3;

    if (tid < 128) { smrow[tid] = 0.0f; smcol[tid] = 0.0f; }

    // ---- load both tiles via one cp.async group (int8: 16KB each)
    {
        const uint4* ga = reinterpret_cast<const uint4*>(g_v8) + (size_t)rb * 1024;
        const uint4* gb = reinterpret_cast<const uint4*>(g_v8) + (size_t)cb * 1024;
#pragma unroll
        for (int i = 0; i < 4; i++) {
            int idx = tid + i * 256;           // 0..1023
            int row = idx >> 3, ch = idx & 7;
            cp_async16(sw_addr(SA, row, ch), ga + row * 8 + ch);
            if (!self_tile)
                cp_async16(sw_addr(SB, row, ch), gb + row * 8 + ch);
        }
        asm volatile("cp.async.commit_group;" ::: "memory");
    }

    const int g2 = lane >> 3;
    const int arow_off = (lane & 7) + ((g2 & 1) << 3);
    const int achunk_off = g2 >> 1;
    // B ldmatrix addressing: tile j = lane>>3 covers (nt = j>>1, chunk parity j&1)
    const int brow_off = ((g2 >> 1) << 3) + (lane & 7);  // 0..15 within half
    const int bchunk_sel = g2 & 1;
    const int lr4 = lane >> 2;
    const int lc2 = (lane & 3) * 2;

    asm volatile("cp.async.wait_group 0;" ::: "memory");
    __syncthreads();

#pragma unroll
    for (int half = 0; half < 2; half++) {
        const int colbase = wc * 32 + half * 16;   // warp's 16-col half

        int32_t acc[4][2][4];
#pragma unroll
        for (int mt = 0; mt < 4; mt++)
#pragma unroll
            for (int nt = 0; nt < 2; nt++)
#pragma unroll
                for (int r = 0; r < 4; r++) acc[mt][nt][r] = 0;

        const int brow = colbase + brow_off;

#pragma unroll
        for (int kp = 0; kp < 4; kp++) {       // K=32 per step
            uint32_t afr[4][4];
#pragma unroll
            for (int mt = 0; mt < 4; mt++) {
                int row = wr * 64 + mt * 16 + arow_off;
                ldsm_x4(afr[mt], sw_addr(SA, row, 2 * kp + achunk_off));
            }
            // one ldmatrix.x4 delivers b0/b1 for both nt groups
            uint32_t bfr[4];
            ldsm_x4(bfr, sw_addr(SB, brow, 2 * kp + bchunk_sel));
#pragma unroll
            for (int mt = 0; mt < 4; mt++) {
                mma_s8(acc[mt][0], afr[mt], bfr[0], bfr[1]);
                mma_s8(acc[mt][1], afr[mt], bfr[2], bfr[3]);
            }
        }

        // -------- epilogue for this half --------
        if (self_tile | pos_tile) {
            float csA[2] = {0.f, 0.f}, csB[2] = {0.f, 0.f};
#pragma unroll
            for (int mt = 0; mt < 4; mt++) {
                float rs0 = 0.0f, rs1 = 0.0f;
                int lrow0 = wr * 64 + mt * 16 + lr4;
#pragma unroll
                for (int nt = 0; nt < 2; nt++) {
                    float v0 = (float)acc[mt][nt][0] * INVQ;
                    float v1 = (float)acc[mt][nt][1] * INVQ;
                    float v2 = (float)acc[mt][nt][2] * INVQ;
                    float v3 = (float)acc[mt][nt][3] * INVQ;
                    float e0 = exp2f(v0), e1 = exp2f(v1);
                    float e2 = exp2f(v2), e3 = exp2f(v3);
                    int lcol0 = colbase + nt * 8 + lc2;
                    if (self_tile) {
                        if (lcol0 == lrow0) e0 = 0.0f;
                        if (lcol0 + 1 == lrow0) e1 = 0.0f;
                        if (lcol0 == lrow0 + 8) e2 = 0.0f;
                        if (lcol0 + 1 == lrow0 + 8) e3 = 0.0f;
                    } else {
                        int grR = rb * 128 + lrow0;
                        int grC = cb * 128 + lrow0;
                        if (lcol0 == lrow0)     { float p2 = v0 * LN2F; g_pos[grR] = p2; g_pos[grC] = p2; }
                        if (lcol0 + 1 == lrow0) { float p2 = v1 * LN2F; g_pos[grR] = p2; g_pos[grC] = p2; }
                        if (lcol0 == lrow0 + 8)     { float p2 = v2 * LN2F; g_pos[grR + 8] = p2; g_pos[grC + 8] = p2; }
                        if (lcol0 + 1 == lrow0 + 8) { float p2 = v3 * LN2F; g_pos[grR + 8] = p2; g_pos[grC + 8] = p2; }
                    }
                    rs0 += e0 + e1;
                    rs1 += e2 + e3;
                    csA[nt] += e0 + e2;
                    csB[nt] += e1 + e3;
                }
                rs0 += __shfl_xor_sync(0xffffffffu, rs0, 1);
                rs0 += __shfl_xor_sync(0xffffffffu, rs0, 2);
                rs1 += __shfl_xor_sync(0xffffffffu, rs1, 1);
                rs1 += __shfl_xor_sync(0xffffffffu, rs1, 2);
                if ((lane & 3) == 0) {
                    atomicAdd(&smrow[lrow0], rs0);
                    atomicAdd(&smrow[lrow0 + 8], rs1);
                }
            }
            if (!self_tile) {
#pragma unroll
                for (int nt = 0; nt < 2; nt++) {
                    float a = csA[nt], b2 = csB[nt];
#pragma unroll
                    for (int o = 4; o <= 16; o <<= 1) {
                        a += __shfl_xor_sync(0xffffffffu, a, o);
                        b2 += __shfl_xor_sync(0xffffffffu, b2, o);
                    }
                    if (lane < 4) {
                        int col = colbase + nt * 8 + lane * 2;
                        atomicAdd(&smcol[col], a);
                        atomicAdd(&smcol[col + 1], b2);
                    }
                }
            }
        } else {
            uint32_t cs[2] = {0u, 0u};
#pragma unroll
            for (int mt = 0; mt < 4; mt++) {
                uint32_t rp0 = 0u, rp1 = 0u;
#pragma unroll
                for (int nt = 0; nt < 2; nt++) {
                    float v0 = (float)acc[mt][nt][0] * INVQ;
                    float v1 = (float)acc[mt][nt][1] * INVQ;
                    float v2 = (float)acc[mt][nt][2] * INVQ;
                    float v3 = (float)acc[mt][nt][3] * INVQ;
                    uint32_t e0 = ex2h2(pack_h2(v0, v1));
                    uint32_t e1 = ex2h2(pack_h2(v2, v3));
                    rp0 = hadd2(rp0, e0);
                    rp1 = hadd2(rp1, e1);
                    cs[nt] = hadd2(cs[nt], hadd2(e0, e1));
                }
                float2 f0 = h22f2(rp0);
                float2 f1 = h22f2(rp1);
                float rs0 = f0.x + f0.y, rs1 = f1.x + f1.y;
                rs0 += __shfl_xor_sync(0xffffffffu, rs0, 1);
                rs0 += __shfl_xor_sync(0xffffffffu, rs0, 2);
                rs1 += __shfl_xor_sync(0xffffffffu, rs1, 1);
                rs1 += __shfl_xor_sync(0xffffffffu, rs1, 2);
                int lrow0 = wr * 64 + mt * 16 + lr4;
                if ((lane & 3) == 0) {
                    atomicAdd(&smrow[lrow0], rs0);
                    atomicAdd(&smrow[lrow0 + 8], rs1);
                }
            }
#pragma unroll
            for (int nt = 0; nt < 2; nt++) {
                float2 cf = h22f2(cs[nt]);
                float a = cf.x, b2 = cf.y;
#pragma unroll
                for (int o = 4; o <= 16; o <<= 1) {
                    a += __shfl_xor_sync(0xffffffffu, a, o);
                    b2 += __shfl_xor_sync(0xffffffffu, b2, o);
                }
                if (lane < 4) {
                    int col = colbase + nt * 8 + lane * 2;
                    atomicAdd(&smcol[col], a);
                    atomicAdd(&smcol[col + 1], b2);
                }
            }
        }
    }

    __syncthreads();
    if (tid < 128) {
        atomicAdd(&g_rowsum[rb * 128 + tid], smrow[tid]);
        if (!self_tile) atomicAdd(&g_rowsum[cb * 128 + tid], smcol[tid]);
    }

    // -------- last-CTA fused reduction --------
    __threadfence();
    __syncthreads();
    if (tid == 0) s_last = (atomicAdd(&g_ctr, 1u) == NWORK - 1u);
    __syncthreads();
    if (s_last) {
        float part = 0.0f;
        for (int i = tid; i < N_TOT; i += 256)
            part += logf(g_rowsum[i]) - g_pos[i];
#pragma unroll
        for (int o = 16; o; o >>= 1) part += __shfl_xor_sync(0xffffffffu, part, o);
        if (lane == 0) smrow[wid] = part;
        __syncthreads();
        if (tid == 0) {
            float s = 0.0f;
#pragma unroll
            for (int w = 0; w < 8; w++) s += smrow[w];
            out[0] = s * (1.0f / (float)N_TOT);
        }
    }
}

// ---------------- launch ----------------
extern "C" void kernel_launch(void* const* d_in, const int* in_sizes, int n_in,
                              void* d_out, int out_size) {
    const float* zi = (const float*)d_in[0];
    const float* zj = (const float*)d_in[1];
    float* out = (float*)d_out;

    cudaFuncSetAttribute(simclr_mma_k,
                         cudaFuncAttributeMaxDynamicSharedMemorySize, SMEM_BYTES);

    normalize_k<<<(N_TOT * 32 + 255) / 256, 256>>>(zi, zj);
    dim3 grid(64, 33);
    simclr_mma_k<<<grid, 256, SMEM_BYTES>>>(out);
}

// round 13
// speedup vs baseline: 1.4230x; 1.0447x over previous
#include <cuda_runtime.h>
#include <cuda_fp16.h>
#include <math.h>
#include <stdint.h>

#define N_TOT 8192
#define B_HALF 4096
#define D 128
#define NWORK 2080
// sqrt(log2(e)/T), T=0.5: fold temperature+log2e into normalization so the
// Gram accumulator is sim in log2-units: exp(sim)=ex2(acc), sim=acc*ln2.
#define VSCALE 1.6986436f
#define LN2F 0.69314718055994531f
#define S8Q 74.0f
#define INVQ 1.8261504e-4f   // 1/(74*74): s32 dot -> log2-units

// ---------------- device globals ----------------
__device__ uint32_t g_v8[N_TOT * 32];      // int8 rows, 128 B each
__device__ float g_rowsum[N_TOT];
__device__ float g_pos[N_TOT];
__device__ unsigned int g_ctr;

// ---------------- helpers ----------------
__device__ __forceinline__ uint32_t smem_u32(const void* p) {
    uint32_t a;
    asm("{ .reg .u64 t; cvta.to.shared.u64 t, %1; cvt.u32.u64 %0, t; }" : "=r"(a) : "l"(p));
    return a;
}
__device__ __forceinline__ uint32_t pack_h2(float lo, float hi) {
    uint32_t d; asm("cvt.rn.f16x2.f32 %0, %1, %2;" : "=r"(d) : "f"(hi), "f"(lo)); return d;
}
__device__ __forceinline__ uint32_t ex2h2(uint32_t x) {
    uint32_t y; asm("ex2.approx.f16x2 %0, %1;" : "=r"(y) : "r"(x)); return y;
}
__device__ __forceinline__ uint32_t hadd2(uint32_t a, uint32_t b) {
    uint32_t d; asm("add.rn.f16x2 %0, %1, %2;" : "=r"(d) : "r"(a), "r"(b)); return d;
}
__device__ __forceinline__ float2 h22f2(uint32_t u) {
    __half2 h = *reinterpret_cast<__half2*>(&u);
    return __half22float2(h);
}
__device__ __forceinline__ void ldsm_x4(uint32_t* r, uint32_t a) {
    asm volatile("ldmatrix.sync.aligned.m8n8.x4.shared.b16 {%0,%1,%2,%3}, [%4];"
                 : "=r"(r[0]), "=r"(r[1]), "=r"(r[2]), "=r"(r[3]) : "r"(a));
}
// int8 MMA, exact s32 accumulate, K=32 per instruction
__device__ __forceinline__ void mma_s8(int32_t* d, const uint32_t* a,
                                       uint32_t b0, uint32_t b1) {
    asm volatile(
        "mma.sync.aligned.m16n8k32.row.col.s32.s8.s8.s32 "
        "{%0,%1,%2,%3}, {%4,%5,%6,%7}, {%8,%9}, {%0,%1,%2,%3};"
        : "+r"(d[0]), "+r"(d[1]), "+r"(d[2]), "+r"(d[3])
        : "r"(a[0]), "r"(a[1]), "r"(a[2]), "r"(a[3]), "r"(b0), "r"(b1));
}
__device__ __forceinline__ void cp_async16(uint32_t saddr, const void* gptr) {
    asm volatile("cp.async.cg.shared.global [%0], [%1], 16;"
                 :: "r"(saddr), "l"(gptr) : "memory");
}

// tile: 128 rows x 128 int8 (128B/row), 8 chunks of 16B, XOR-swizzled
__device__ __forceinline__ uint32_t sw_addr(uint32_t base, int row, int chunk) {
    return base + row * 128 + (((chunk ^ row) & 7) << 4);
}

// ---------------- kernels ----------------
__global__ void normalize_k(const float* __restrict__ zi,
                            const float* __restrict__ zj) {
    int gt = blockIdx.x * blockDim.x + threadIdx.x;
    int warp = gt >> 5, lane = gt & 31;
    if (gt < N_TOT) g_rowsum[gt] = 0.0f;
    if (gt == 0) g_ctr = 0u;
    if (warp >= N_TOT) return;
    const float* src = (warp < B_HALF) ? (zi + (size_t)warp * D)
                                       : (zj + (size_t)(warp - B_HALF) * D);
    float4 a = reinterpret_cast<const float4*>(src)[lane];
    float ss = a.x * a.x + a.y * a.y + a.z * a.z + a.w * a.w;
#pragma unroll
    for (int o = 16; o; o >>= 1) ss += __shfl_xor_sync(0xffffffffu, ss, o);
    float s = (VSCALE * S8Q) / fmaxf(sqrtf(ss), 1e-8f);
    int i0 = __float2int_rn(a.x * s), i1 = __float2int_rn(a.y * s);
    int i2 = __float2int_rn(a.z * s), i3 = __float2int_rn(a.w * s);
    uint32_t pk = (i0 & 0xff) | ((i1 & 0xff) << 8) | ((i2 & 0xff) << 16)
                | ((uint32_t)(i3 & 0xff) << 24);
    g_v8[warp * 32 + lane] = pk;
}

// smem: A tile 16KB | B tile 16KB
#define SMEM_BYTES 32768

// 256 threads = 8 warps (2x4); warp computes 64x32, processed as two 64x16
// column halves over full K (keeps s32 acc register count at 32).
// 4 CTAs/SM: forces <=64 regs; k-loop live set ~62 so no hot-loop spills.
__global__ void __launch_bounds__(256, 4) simclr_mma_k(float* __restrict__ out) {
    // wrapped-diagonal triangle map: each unordered block pair exactly once
    int x = blockIdx.x, y = blockIdx.y;
    if (y == 32 && x >= 32) return;
    int c = (x + y) & 63;
    const int rb = min(x, c), cb = max(x, c);

    extern __shared__ char dynsm[];
    __shared__ float smrow[128];
    __shared__ float smcol[128];
    __shared__ unsigned int s_last;
    const uint32_t SA = smem_u32(dynsm);
    const bool self_tile = (rb == cb);
    const bool pos_tile = (cb == rb + 32);
    const uint32_t SB = self_tile ? SA : SA + 16384;

    const int tid = threadIdx.x, wid = tid >> 5, lane = tid & 31;
    const int wr = wid >> 2, wc = wid & 3;

    if (tid < 128) { smrow[tid] = 0.0f; smcol[tid] = 0.0f; }

    // ---- load both tiles via one cp.async group (int8: 16KB each)
    {
        const uint4* ga = reinterpret_cast<const uint4*>(g_v8) + (size_t)rb * 1024;
        const uint4* gb = reinterpret_cast<const uint4*>(g_v8) + (size_t)cb * 1024;
#pragma unroll
        for (int i = 0; i < 4; i++) {
            int idx = tid + i * 256;           // 0..1023
            int row = idx >> 3, ch = idx & 7;
            cp_async16(sw_addr(SA, row, ch), ga + row * 8 + ch);
            if (!self_tile)
                cp_async16(sw_addr(SB, row, ch), gb + row * 8 + ch);
        }
        asm volatile("cp.async.commit_group;" ::: "memory");
    }

    const int g2 = lane >> 3;
    const int arow_off = (lane & 7) + ((g2 & 1) << 3);
    const int achunk_off = g2 >> 1;
    // B ldmatrix addressing: tile j = lane>>3 covers (nt = j>>1, chunk parity j&1)
    const int brow_off = ((g2 >> 1) << 3) + (lane & 7);  // 0..15 within half
    const int bchunk_sel = g2 & 1;
    const int lr4 = lane >> 2;
    const int lc2 = (lane & 3) * 2;

    asm volatile("cp.async.wait_group 0;" ::: "memory");
    __syncthreads();

#pragma unroll
    for (int half = 0; half < 2; half++) {
        const int colbase = wc * 32 + half * 16;   // warp's 16-col half

        int32_t acc[4][2][4];
#pragma unroll
        for (int mt = 0; mt < 4; mt++)
#pragma unroll
            for (int nt = 0; nt < 2; nt++)
#pragma unroll
                for (int r = 0; r < 4; r++) acc[mt][nt][r] = 0;

        const int brow = colbase + brow_off;

#pragma unroll
        for (int kp = 0; kp < 4; kp++) {       // K=32 per step
            uint32_t afr[4][4];
#pragma unroll
            for (int mt = 0; mt < 4; mt++) {
                int row = wr * 64 + mt * 16 + arow_off;
                ldsm_x4(afr[mt], sw_addr(SA, row, 2 * kp + achunk_off));
            }
            // one ldmatrix.x4 delivers b0/b1 for both nt groups
            uint32_t bfr[4];
            ldsm_x4(bfr, sw_addr(SB, brow, 2 * kp + bchunk_sel));
#pragma unroll
            for (int mt = 0; mt < 4; mt++) {
                mma_s8(acc[mt][0], afr[mt], bfr[0], bfr[1]);
                mma_s8(acc[mt][1], afr[mt], bfr[2], bfr[3]);
            }
        }

        // -------- epilogue for this half --------
        if (self_tile | pos_tile) {
            float csA[2] = {0.f, 0.f}, csB[2] = {0.f, 0.f};
#pragma unroll
            for (int mt = 0; mt < 4; mt++) {
                float rs0 = 0.0f, rs1 = 0.0f;
                int lrow0 = wr * 64 + mt * 16 + lr4;
#pragma unroll
                for (int nt = 0; nt < 2; nt++) {
                    float v0 = (float)acc[mt][nt][0] * INVQ;
                    float v1 = (float)acc[mt][nt][1] * INVQ;
                    float v2 = (float)acc[mt][nt][2] * INVQ;
                    float v3 = (float)acc[mt][nt][3] * INVQ;
                    float e0 = exp2f(v0), e1 = exp2f(v1);
                    float e2 = exp2f(v2), e3 = exp2f(v3);
                    int lcol0 = colbase + nt * 8 + lc2;
                    if (self_tile) {
                        if (lcol0 == lrow0) e0 = 0.0f;
                        if (lcol0 + 1 == lrow0) e1 = 0.0f;
                        if (lcol0 == lrow0 + 8) e2 = 0.0f;
                        if (lcol0 + 1 == lrow0 + 8) e3 = 0.0f;
                    } else {
                        int grR = rb * 128 + lrow0;
                        int grC = cb * 128 + lrow0;
                        if (lcol0 == lrow0)     { float p2 = v0 * LN2F; g_pos[grR] = p2; g_pos[grC] = p2; }
                        if (lcol0 + 1 == lrow0) { float p2 = v1 * LN2F; g_pos[grR] = p2; g_pos[grC] = p2; }
                        if (lcol0 == lrow0 + 8)     { float p2 = v2 * LN2F; g_pos[grR + 8] = p2; g_pos[grC + 8] = p2; }
                        if (lcol0 + 1 == lrow0 + 8) { float p2 = v3 * LN2F; g_pos[grR + 8] = p2; g_pos[grC + 8] = p2; }
                    }
                    rs0 += e0 + e1;
                    rs1 += e2 + e3;
                    csA[nt] += e0 + e2;
                    csB[nt] += e1 + e3;
                }
                rs0 += __shfl_xor_sync(0xffffffffu, rs0, 1);
                rs0 += __shfl_xor_sync(0xffffffffu, rs0, 2);
                rs1 += __shfl_xor_sync(0xffffffffu, rs1, 1);
                rs1 += __shfl_xor_sync(0xffffffffu, rs1, 2);
                if ((lane & 3) == 0) {
                    atomicAdd(&smrow[lrow0], rs0);
                    atomicAdd(&smrow[lrow0 + 8], rs1);
                }
            }
            if (!self_tile) {
#pragma unroll
                for (int nt = 0; nt < 2; nt++) {
                    float a = csA[nt], b2 = csB[nt];
#pragma unroll
                    for (int o = 4; o <= 16; o <<= 1) {
                        a += __shfl_xor_sync(0xffffffffu, a, o);
                        b2 += __shfl_xor_sync(0xffffffffu, b2, o);
                    }
                    if (lane < 4) {
                        int col = colbase + nt * 8 + lane * 2;
                        atomicAdd(&smcol[col], a);
                        atomicAdd(&smcol[col + 1], b2);
                    }
                }
            }
        } else {
            uint32_t cs[2] = {0u, 0u};
#pragma unroll
            for (int mt = 0; mt < 4; mt++) {
                uint32_t rp0 = 0u, rp1 = 0u;
#pragma unroll
                for (int nt = 0; nt < 2; nt++) {
                    float v0 = (float)acc[mt][nt][0] * INVQ;
                    float v1 = (float)acc[mt][nt][1] * INVQ;
                    float v2 = (float)acc[mt][nt][2] * INVQ;
                    float v3 = (float)acc[mt][nt][3] * INVQ;
                    uint32_t e0 = ex2h2(pack_h2(v0, v1));
                    uint32_t e1 = ex2h2(pack_h2(v2, v3));
                    rp0 = hadd2(rp0, e0);
                    rp1 = hadd2(rp1, e1);
                    cs[nt] = hadd2(cs[nt], hadd2(e0, e1));
                }
                float2 f0 = h22f2(rp0);
                float2 f1 = h22f2(rp1);
                float rs0 = f0.x + f0.y, rs1 = f1.x + f1.y;
                rs0 += __shfl_xor_sync(0xffffffffu, rs0, 1);
                rs0 += __shfl_xor_sync(0xffffffffu, rs0, 2);
                rs1 += __shfl_xor_sync(0xffffffffu, rs1, 1);
                rs1 += __shfl_xor_sync(0xffffffffu, rs1, 2);
                int lrow0 = wr * 64 + mt * 16 + lr4;
                if ((lane & 3) == 0) {
                    atomicAdd(&smrow[lrow0], rs0);
                    atomicAdd(&smrow[lrow0 + 8], rs1);
                }
            }
#pragma unroll
            for (int nt = 0; nt < 2; nt++) {
                float2 cf = h22f2(cs[nt]);
                float a = cf.x, b2 = cf.y;
#pragma unroll
                for (int o = 4; o <= 16; o <<= 1) {
                    a += __shfl_xor_sync(0xffffffffu, a, o);
                    b2 += __shfl_xor_sync(0xffffffffu, b2, o);
                }
                if (lane < 4) {
                    int col = colbase + nt * 8 + lane * 2;
                    atomicAdd(&smcol[col], a);
                    atomicAdd(&smcol[col + 1], b2);
                }
            }
        }
    }

    __syncthreads();
    if (tid < 128) {
        atomicAdd(&g_rowsum[rb * 128 + tid], smrow[tid]);
        if (!self_tile) atomicAdd(&g_rowsum[cb * 128 + tid], smcol[tid]);
    }

    // -------- last-CTA fused reduction --------
    // syncthreads establishes CTA-wide happens-before; tid0's gpu-scope fence
    // is cumulative over those edges, so one fence orders all 128 global adds.
    __syncthreads();
    if (tid == 0) {
        __threadfence();
        s_last = (atomicAdd(&g_ctr, 1u) == NWORK - 1u);
    }
    __syncthreads();
    if (s_last) {
        float part = 0.0f;
        for (int i = tid; i < N_TOT; i += 256)
            part += logf(g_rowsum[i]) - g_pos[i];
#pragma unroll
        for (int o = 16; o; o >>= 1) part += __shfl_xor_sync(0xffffffffu, part, o);
        if (lane == 0) smrow[wid] = part;
        __syncthreads();
        if (tid == 0) {
            float s = 0.0f;
#pragma unroll
            for (int w = 0; w < 8; w++) s += smrow[w];
            out[0] = s * (1.0f / (float)N_TOT);
        }
    }
}

// ---------------- launch ----------------
extern "C" void kernel_launch(void* const* d_in, const int* in_sizes, int n_in,
                              void* d_out, int out_size) {
    const float* zi = (const float*)d_in[0];
    const float* zj = (const float*)d_in[1];
    float* out = (float*)d_out;

    cudaFuncSetAttribute(simclr_mma_k,
                         cudaFuncAttributeMaxDynamicSharedMemorySize, SMEM_BYTES);

    normalize_k<<<(N_TOT * 32 + 255) / 256, 256>>>(zi, zj);
    dim3 grid(64, 33);
    simclr_mma_k<<<grid, 256, SMEM_BYTES>>>(out);
}

// round 14
// speedup vs baseline: 1.5305x; 1.0756x over previous
#include <cuda_runtime.h>
#include <cuda_fp16.h>
#include <math.h>
#include <stdint.h>

#define N_TOT 8192
#define B_HALF 4096
#define D 128
#define NWORK 1056u
// sqrt(log2(e)/T), T=0.5: fold temperature+log2e into normalization so the
// Gram accumulator is sim in log2-units: exp(sim)=ex2(acc), sim=acc*ln2.
#define VSCALE 1.6986436f
#define LN2F 0.69314718055994531f
#define S8Q 74.0f
#define INVQ 1.8261504e-4f   // 1/(74*74): s32 dot -> log2-units

// ---------------- device globals ----------------
__device__ uint32_t g_v8[N_TOT * 32];      // int8 rows, 128 B each
__device__ float g_rowsum[N_TOT];
__device__ float g_pos[N_TOT];
__device__ unsigned int g_ctr;

// ---------------- helpers ----------------
__device__ __forceinline__ uint32_t smem_u32(const void* p) {
    uint32_t a;
    asm("{ .reg .u64 t; cvta.to.shared.u64 t, %1; cvt.u32.u64 %0, t; }" : "=r"(a) : "l"(p));
    return a;
}
__device__ __forceinline__ uint32_t pack_h2(float lo, float hi) {
    uint32_t d; asm("cvt.rn.f16x2.f32 %0, %1, %2;" : "=r"(d) : "f"(hi), "f"(lo)); return d;
}
__device__ __forceinline__ uint32_t ex2h2(uint32_t x) {
    uint32_t y; asm("ex2.approx.f16x2 %0, %1;" : "=r"(y) : "r"(x)); return y;
}
__device__ __forceinline__ uint32_t hadd2(uint32_t a, uint32_t b) {
    uint32_t d; asm("add.rn.f16x2 %0, %1, %2;" : "=r"(d) : "r"(a), "r"(b)); return d;
}
__device__ __forceinline__ float2 h22f2(uint32_t u) {
    __half2 h = *reinterpret_cast<__half2*>(&u);
    return __half22float2(h);
}
__device__ __forceinline__ void ldsm_x4(uint32_t* r, uint32_t a) {
    asm volatile("ldmatrix.sync.aligned.m8n8.x4.shared.b16 {%0,%1,%2,%3}, [%4];"
                 : "=r"(r[0]), "=r"(r[1]), "=r"(r[2]), "=r"(r[3]) : "r"(a));
}
// int8 MMA, exact s32 accumulate, K=32 per instruction
__device__ __forceinline__ void mma_s8(int32_t* d, const uint32_t* a,
                                       uint32_t b0, uint32_t b1) {
    asm volatile(
        "mma.sync.aligned.m16n8k32.row.col.s32.s8.s8.s32 "
        "{%0,%1,%2,%3}, {%4,%5,%6,%7}, {%8,%9}, {%0,%1,%2,%3};"
        : "+r"(d[0]), "+r"(d[1]), "+r"(d[2]), "+r"(d[3])
        : "r"(a[0]), "r"(a[1]), "r"(a[2]), "r"(a[3]), "r"(b0), "r"(b1));
}
__device__ __forceinline__ void cp_async16(uint32_t saddr, const void* gptr) {
    asm volatile("cp.async.cg.shared.global [%0], [%1], 16;"
                 :: "r"(saddr), "l"(gptr) : "memory");
}

// tile: 128 rows x 128 int8 (128B/row), 8 chunks of 16B, XOR-swizzled
__device__ __forceinline__ uint32_t sw_addr(uint32_t base, int row, int chunk) {
    return base + row * 128 + (((chunk ^ row) & 7) << 4);
}

// ---------------- kernels ----------------
__global__ void normalize_k(const float* __restrict__ zi,
                            const float* __restrict__ zj) {
    int gt = blockIdx.x * blockDim.x + threadIdx.x;
    int warp = gt >> 5, lane = gt & 31;
    if (gt < N_TOT) g_rowsum[gt] = 0.0f;
    if (gt == 0) g_ctr = 0u;
    if (warp >= N_TOT) return;
    const float* src = (warp < B_HALF) ? (zi + (size_t)warp * D)
                                       : (zj + (size_t)(warp - B_HALF) * D);
    float4 a = reinterpret_cast<const float4*>(src)[lane];
    float ss = a.x * a.x + a.y * a.y + a.z * a.z + a.w * a.w;
#pragma unroll
    for (int o = 16; o; o >>= 1) ss += __shfl_xor_sync(0xffffffffu, ss, o);
    float s = (VSCALE * S8Q) / fmaxf(sqrtf(ss), 1e-8f);
    int i0 = __float2int_rn(a.x * s), i1 = __float2int_rn(a.y * s);
    int i2 = __float2int_rn(a.z * s), i3 = __float2int_rn(a.w * s);
    uint32_t pk = (i0 & 0xff) | ((i1 & 0xff) << 8) | ((i2 & 0xff) << 16)
                | ((uint32_t)(i3 & 0xff) << 24);
    g_v8[warp * 32 + lane] = pk;
}

// one 128x128 tile: k-loop + epilogue (r13-proven body)
__device__ __forceinline__ void compute_tile(
    uint32_t SA, uint32_t SB, int rb, int cb, bool self_tile, bool pos_tile,
    int wr, int wc, int lane, float* smrow, float* smcol)
{
    const int g2 = lane >> 3;
    const int arow_off = (lane & 7) + ((g2 & 1) << 3);
    const int achunk_off = g2 >> 1;
    const int brow_off = ((g2 >> 1) << 3) + (lane & 7);
    const int bchunk_sel = g2 & 1;
    const int lr4 = lane >> 2;
    const int lc2 = (lane & 3) * 2;

#pragma unroll
    for (int half = 0; half < 2; half++) {
        const int colbase = wc * 32 + half * 16;   // warp's 16-col half

        int32_t acc[4][2][4];
#pragma unroll
        for (int mt = 0; mt < 4; mt++)
#pragma unroll
            for (int nt = 0; nt < 2; nt++)
#pragma unroll
                for (int r = 0; r < 4; r++) acc[mt][nt][r] = 0;

        const int brow = colbase + brow_off;

#pragma unroll
        for (int kp = 0; kp < 4; kp++) {       // K=32 per step
            uint32_t afr[4][4];
#pragma unroll
            for (int mt = 0; mt < 4; mt++) {
                int row = wr * 64 + mt * 16 + arow_off;
                ldsm_x4(afr[mt], sw_addr(SA, row, 2 * kp + achunk_off));
            }
            uint32_t bfr[4];
            ldsm_x4(bfr, sw_addr(SB, brow, 2 * kp + bchunk_sel));
#pragma unroll
            for (int mt = 0; mt < 4; mt++) {
                mma_s8(acc[mt][0], afr[mt], bfr[0], bfr[1]);
                mma_s8(acc[mt][1], afr[mt], bfr[2], bfr[3]);
            }
        }

        // -------- epilogue for this half --------
        if (self_tile | pos_tile) {
            float csA[2] = {0.f, 0.f}, csB[2] = {0.f, 0.f};
#pragma unroll
            for (int mt = 0; mt < 4; mt++) {
                float rs0 = 0.0f, rs1 = 0.0f;
                int lrow0 = wr * 64 + mt * 16 + lr4;
#pragma unroll
                for (int nt = 0; nt < 2; nt++) {
                    float v0 = (float)acc[mt][nt][0] * INVQ;
                    float v1 = (float)acc[mt][nt][1] * INVQ;
                    float v2 = (float)acc[mt][nt][2] * INVQ;
                    float v3 = (float)acc[mt][nt][3] * INVQ;
                    float e0 = exp2f(v0), e1 = exp2f(v1);
                    float e2 = exp2f(v2), e3 = exp2f(v3);
                    int lcol0 = colbase + nt * 8 + lc2;
                    if (self_tile) {
                        if (lcol0 == lrow0) e0 = 0.0f;
                        if (lcol0 + 1 == lrow0) e1 = 0.0f;
                        if (lcol0 == lrow0 + 8) e2 = 0.0f;
                        if (lcol0 + 1 == lrow0 + 8) e3 = 0.0f;
                    } else {
                        int grR = rb * 128 + lrow0;
                        int grC = cb * 128 + lrow0;
                        if (lcol0 == lrow0)     { float p2 = v0 * LN2F; g_pos[grR] = p2; g_pos[grC] = p2; }
                        if (lcol0 + 1 == lrow0) { float p2 = v1 * LN2F; g_pos[grR] = p2; g_pos[grC] = p2; }
                        if (lcol0 == lrow0 + 8)     { float p2 = v2 * LN2F; g_pos[grR + 8] = p2; g_pos[grC + 8] = p2; }
                        if (lcol0 + 1 == lrow0 + 8) { float p2 = v3 * LN2F; g_pos[grR + 8] = p2; g_pos[grC + 8] = p2; }
                    }
                    rs0 += e0 + e1;
                    rs1 += e2 + e3;
                    csA[nt] += e0 + e2;
                    csB[nt] += e1 + e3;
                }
                rs0 += __shfl_xor_sync(0xffffffffu, rs0, 1);
                rs0 += __shfl_xor_sync(0xffffffffu, rs0, 2);
                rs1 += __shfl_xor_sync(0xffffffffu, rs1, 1);
                rs1 += __shfl_xor_sync(0xffffffffu, rs1, 2);
                if ((lane & 3) == 0) {
                    atomicAdd(&smrow[lrow0], rs0);
                    atomicAdd(&smrow[lrow0 + 8], rs1);
                }
            }
            if (!self_tile) {
#pragma unroll
                for (int nt = 0; nt < 2; nt++) {
                    float a = csA[nt], b2 = csB[nt];
#pragma unroll
                    for (int o = 4; o <= 16; o <<= 1) {
                        a += __shfl_xor_sync(0xffffffffu, a, o);
                        b2 += __shfl_xor_sync(0xffffffffu, b2, o);
                    }
                    if (lane < 4) {
                        int col = colbase + nt * 8 + lane * 2;
                        atomicAdd(&smcol[col], a);
                        atomicAdd(&smcol[col + 1], b2);
                    }
                }
            }
        } else {
            uint32_t cs[2] = {0u, 0u};
#pragma unroll
            for (int mt = 0; mt < 4; mt++) {
                uint32_t rp0 = 0u, rp1 = 0u;
#pragma unroll
                for (int nt = 0; nt < 2; nt++) {
                    float v0 = (float)acc[mt][nt][0] * INVQ;
                    float v1 = (float)acc[mt][nt][1] * INVQ;
                    float v2 = (float)acc[mt][nt][2] * INVQ;
                    float v3 = (float)acc[mt][nt][3] * INVQ;
                    uint32_t e0 = ex2h2(pack_h2(v0, v1));
                    uint32_t e1 = ex2h2(pack_h2(v2, v3));
                    rp0 = hadd2(rp0, e0);
                    rp1 = hadd2(rp1, e1);
                    cs[nt] = hadd2(cs[nt], hadd2(e0, e1));
                }
                float2 f0 = h22f2(rp0);
                float2 f1 = h22f2(rp1);
                float rs0 = f0.x + f0.y, rs1 = f1.x + f1.y;
                rs0 += __shfl_xor_sync(0xffffffffu, rs0, 1);
                rs0 += __shfl_xor_sync(0xffffffffu, rs0, 2);
                rs1 += __shfl_xor_sync(0xffffffffu, rs1, 1);
                rs1 += __shfl_xor_sync(0xffffffffu, rs1, 2);
                int lrow0 = wr * 64 + mt * 16 + lr4;
                if ((lane & 3) == 0) {
                    atomicAdd(&smrow[lrow0], rs0);
                    atomicAdd(&smrow[lrow0 + 8], rs1);
                }
            }
#pragma unroll
            for (int nt = 0; nt < 2; nt++) {
                float2 cf = h22f2(cs[nt]);
                float a = cf.x, b2 = cf.y;
#pragma unroll
                for (int o = 4; o <= 16; o <<= 1) {
                    a += __shfl_xor_sync(0xffffffffu, a, o);
                    b2 += __shfl_xor_sync(0xffffffffu, b2, o);
                }
                if (lane < 4) {
                    int col = colbase + nt * 8 + lane * 2;
                    atomicAdd(&smcol[col], a);
                    atomicAdd(&smcol[col + 1], b2);
                }
            }
        }
    }
}

// smem: A tile 16KB | B0 16KB | B1 16KB
#define SMEM_BYTES 49152

// 256 threads = 8 warps (2x4); CTA computes tiles (rb,cb0) and (rb,cb0+1)
// sharing the A tile. B1 load overlaps tile-0 compute via cp.async groups.
__global__ void __launch_bounds__(256, 4) simclr_mma_k(float* __restrict__ out) {
    const int px = blockIdx.x, rb = blockIdx.y;
    const int cb0 = rb + 2 * px;
    if (cb0 >= 64) return;
    const bool has2 = (cb0 < 63);
    const bool self0 = (cb0 == rb);
    const bool pos0 = (cb0 == rb + 32);

    extern __shared__ char dynsm[];
    __shared__ float smrow[128];
    __shared__ float smcol0[128];
    __shared__ float smcol1[128];
    __shared__ unsigned int s_last;
    const uint32_t SA = smem_u32(dynsm);
    const uint32_t SB0 = self0 ? SA : SA + 16384;
    const uint32_t SB1 = SA + 32768;

    const int tid = threadIdx.x, wid = tid >> 5, lane = tid & 31;
    const int wr = wid >> 2, wc = wid & 3;

    if (tid < 128) { smrow[tid] = 0.0f; smcol0[tid] = 0.0f; smcol1[tid] = 0.0f; }

    // ---- group 0: A + B0;  group 1: B1 (overlaps tile-0 compute)
    {
        const uint4* ga = reinterpret_cast<const uint4*>(g_v8) + (size_t)rb * 1024;
        const uint4* gb0 = reinterpret_cast<const uint4*>(g_v8) + (size_t)cb0 * 1024;
        const uint4* gb1 = gb0 + 1024;
#pragma unroll
        for (int i = 0; i < 4; i++) {
            int idx = tid + i * 256;
            int row = idx >> 3, ch = idx & 7;
            cp_async16(sw_addr(SA, row, ch), ga + row * 8 + ch);
            if (!self0)
                cp_async16(sw_addr(SB0, row, ch), gb0 + row * 8 + ch);
        }
        asm volatile("cp.async.commit_group;" ::: "memory");
        if (has2) {
#pragma unroll
            for (int i = 0; i < 4; i++) {
                int idx = tid + i * 256;
                int row = idx >> 3, ch = idx & 7;
                cp_async16(sw_addr(SB1, row, ch), gb1 + row * 8 + ch);
            }
        }
        asm volatile("cp.async.commit_group;" ::: "memory");
    }

    asm volatile("cp.async.wait_group 1;" ::: "memory");
    __syncthreads();
    compute_tile(SA, SB0, rb, cb0, self0, pos0, wr, wc, lane, smrow, smcol0);

    if (has2) {
        asm volatile("cp.async.wait_group 0;" ::: "memory");
        __syncthreads();
        compute_tile(SA, SB1, rb, cb0 + 1, false, false, wr, wc, lane, smrow, smcol1);
    }

    __syncthreads();
    if (tid < 128) {
        atomicAdd(&g_rowsum[rb * 128 + tid], smrow[tid]);
        if (!self0) atomicAdd(&g_rowsum[cb0 * 128 + tid], smcol0[tid]);
        if (has2)   atomicAdd(&g_rowsum[(cb0 + 1) * 128 + tid], smcol1[tid]);
    }

    // -------- last-CTA fused reduction --------
    __syncthreads();
    if (tid == 0) {
        __threadfence();
        s_last = (atomicAdd(&g_ctr, 1u) == NWORK - 1u);
    }
    __syncthreads();
    if (s_last) {
        float part = 0.0f;
        for (int i = tid; i < N_TOT; i += 256)
            part += logf(g_rowsum[i]) - g_pos[i];
#pragma unroll
        for (int o = 16; o; o >>= 1) part += __shfl_xor_sync(0xffffffffu, part, o);
        if (lane == 0) smrow[wid] = part;
        __syncthreads();
        if (tid == 0) {
            float s = 0.0f;
#pragma unroll
            for (int w = 0; w < 8; w++) s += smrow[w];
            out[0] = s * (1.0f / (float)N_TOT);
        }
    }
}

// ---------------- launch ----------------
extern "C" void kernel_launch(void* const* d_in, const int* in_sizes, int n_in,
                              void* d_out, int out_size) {
    const float* zi = (const float*)d_in[0];
    const float* zj = (const float*)d_in[1];
    float* out = (float*)d_out;

    cudaFuncSetAttribute(simclr_mma_k,
                         cudaFuncAttributeMaxDynamicSharedMemorySize, SMEM_BYTES);

    normalize_k<<<(N_TOT * 32 + 255) / 256, 256>>>(zi, zj);
    dim3 grid(32, 64);
    simclr_mma_k<<<grid, 256, SMEM_BYTES>>>(out);
}